// round 12
// baseline (speedup 1.0000x reference)
#include <cuda_runtime.h>
#include <math.h>

#define NB   16
#define C    256
#define H    80
#define W    80
#define MIP  8
#define L    160           // H + W
#define BN_EPS 1e-5f

#define GRID 128           // 1 block per SM (<=148): balanced persistent grid
#define TPB  640           // 2 half-blocks of 320; each half owns one channel

// Cross-block state (device globals; init kernel zeroes per launch)
__device__ float g_ys [NB * MIP * L];   // pre-BN bottleneck accumulators, per batch
__device__ int   g_cnt[NB];             // blocks-done counter per batch

__device__ __forceinline__ float fsig(float v) { return 1.f / (1.f + __expf(-v)); }

__device__ __forceinline__ float ldcg(const float* p) {
    float v;
    asm volatile("ld.global.cg.f32 %0, [%1];" : "=f"(v) : "l"(p));
    return v;
}

// SMEM (floats):
//   bufs   : 3 lag-buffers x 2 planes x 1600 float4 = 38400
//   s_row  : 2 x 80*21 = 3360
//   s_col  : 2 x 80*17 = 2720
//   s_mean : 2 x 160   = 320
//   s_ys   : 1280
//   s_ah   : 2 x 80 = 160
//   s_aw   : 2 x 80 = 160
//   s_bn   : 16
#define SM_FLOATS (38400 + 3360 + 2720 + 320 + 1280 + 160 + 160 + 16)  // 46416 -> 185664 B

__global__ void init_state() {
    int i = blockIdx.x * blockDim.x + threadIdx.x;
    if (i < NB * MIP * L) g_ys[i] = 0.f;
    if (i < NB)           g_cnt[i] = 0;
}

__global__ __launch_bounds__(TPB, 1) void fused(const float* __restrict__ x,
                                                const float* __restrict__ w_fc,
                                                const float* __restrict__ bn_gamma,
                                                const float* __restrict__ bn_beta,
                                                const float* __restrict__ bn_mean,
                                                const float* __restrict__ bn_var,
                                                const float* __restrict__ w_h,
                                                const float* __restrict__ w_w,
                                                float* __restrict__ out) {
    extern __shared__ float sm[];
    float4* bufs   = (float4*)sm;              // 9600 float4
    float*  s_row  = sm + 38400;               // 2 x [80][21]
    float*  s_col  = s_row + 3360;             // 2 x [80][17]
    float*  s_mean = s_col + 2720;             // [2][160]
    float*  s_ys   = s_mean + 320;             // [1280]
    float*  s_ah   = s_ys + 1280;              // [2][80]
    float*  s_aw   = s_ah + 160;               // [2][80]
    float*  s_bn   = s_aw + 160;               // [16]

    const int b = blockIdx.x;                  // channel pair id
    const int t = threadIdx.x;
    const int p = t / 320;                     // half: 0 or 1
    const int u = t - p * 320;                 // index within half
    const int q  = u % 20;                     // float4 column group
    const int rg = u / 20;                     // row group 0..15
    const int c  = 2 * b + p;                  // this half's channel

    // Per-thread constants
    float wh[MIP], ww[MIP];
    #pragma unroll
    for (int m = 0; m < MIP; m++) {
        wh[m] = w_h[c * MIP + m];
        ww[m] = w_w[c * MIP + m];
    }
    float wfc0[MIP], wfc1[MIP];
    if (t < L) {
        #pragma unroll
        for (int m = 0; m < MIP; m++) {
            wfc0[m] = w_fc[m * C + 2 * b];
            wfc1[m] = w_fc[m * C + 2 * b + 1];
        }
    }
    if (t < MIP) {
        float iv = bn_gamma[t] * rsqrtf(bn_var[t] + BN_EPS);
        s_bn[t]       = iv;
        s_bn[MIP + t] = bn_beta[t] - bn_mean[t] * iv;
    }

    const float inv80 = 1.0f / 80.0f;
    const float4* __restrict__ x4 = (const float4*)x;
    float4* __restrict__ o4 = (float4*)out;

    // ---- Phase C: consume batch j ----
    auto do_C = [&](int j) {
        if (t == 0) {
            while (*(volatile int*)&g_cnt[j] != GRID) { }
        }
        __syncthreads();
        __threadfence();

        // BN + swish into smem (1280 values, 2 per thread); L2-fresh loads
        const float* __restrict__ ysg = g_ys + j * (MIP * L);
        #pragma unroll
        for (int u2 = 0; u2 < 2; u2++) {
            int idx = t + u2 * TPB;            // [0,1280)
            int m   = idx / L;
            float s = ldcg(ysg + idx);
            float v = s * s_bn[m] + s_bn[MIP + m];
            s_ys[idx] = v * fsig(v);
        }
        __syncthreads();

        // Attention vectors for this half's channel
        if (u < H) {
            float d = 0.f;
            #pragma unroll
            for (int m = 0; m < MIP; m++) d = fmaf(wh[m], s_ys[m * L + u], d);
            s_ah[p * 80 + u] = fsig(d);
        } else if (u >= 160 && u < 160 + W) {
            int l = u - 160;
            float d = 0.f;
            #pragma unroll
            for (int m = 0; m < MIP; m++) d = fmaf(ww[m], s_ys[m * L + H + l], d);
            s_aw[p * 80 + l] = fsig(d);
        }
        __syncthreads();

        // Apply from buffered plane; streaming stores
        const float4* buf = bufs + (j % 3) * 3200 + p * 1600;
        const size_t  ob  = (size_t)(j * C + c) * 1600;
        const float4  aw4 = *(const float4*)(s_aw + p * 80 + 4 * q);
        #pragma unroll
        for (int i = 0; i < 5; i++) {
            int r = i * 16 + rg;
            float4 v  = buf[r * 20 + q];
            float  ah = s_ah[p * 80 + r];
            float4 rr;
            rr.x = v.x * (ah * aw4.x);
            rr.y = v.y * (ah * aw4.y);
            rr.z = v.z * (ah * aw4.z);
            rr.w = v.w * (ah * aw4.w);
            __stcs(o4 + ob + r * 20 + q, rr);
        }
    };

    // ---- Main pipeline: A(k), then C(k-2) ----
    for (int k = 0; k < NB; k++) {
        __syncthreads();                       // buffer (k%3) free; s_row/s_col reuse

        // Phase A: load this half's plane, buffer it, reduce
        const float4* __restrict__ xp = x4 + (size_t)(k * C + c) * 1600;
        float4* buf  = bufs + (k % 3) * 3200 + p * 1600;
        float*  srow = s_row + p * 1680;
        float*  scol = s_col + p * 1360;

        float4 v[5];
        #pragma unroll
        for (int i = 0; i < 5; i++)            // front-batched: 5 LDG.128 in flight
            v[i] = xp[(i * 16 + rg) * 20 + q];

        float4 cacc = make_float4(0.f, 0.f, 0.f, 0.f);
        #pragma unroll
        for (int i = 0; i < 5; i++) {
            int r = i * 16 + rg;
            buf[r * 20 + q] = v[i];
            cacc.x += v[i].x; cacc.y += v[i].y; cacc.z += v[i].z; cacc.w += v[i].w;
            srow[r * 21 + q] = (v[i].x + v[i].y) + (v[i].z + v[i].w);
        }
        scol[(4 * q + 0) * 17 + rg] = cacc.x;
        scol[(4 * q + 1) * 17 + rg] = cacc.y;
        scol[(4 * q + 2) * 17 + rg] = cacc.z;
        scol[(4 * q + 3) * 17 + rg] = cacc.w;
        __syncthreads();

        // Means for this half's channel
        if (u < H) {
            float s = 0.f;
            #pragma unroll
            for (int j2 = 0; j2 < 20; j2++) s += srow[u * 21 + j2];
            s_mean[p * 160 + u] = s * inv80;                 // x_h
        } else if (u >= 160 && u < 160 + W) {
            int col = u - 160;
            float s = 0.f;
            #pragma unroll
            for (int g = 0; g < 16; g++) s += scol[col * 17 + g];
            s_mean[p * 160 + 80 + col] = s * inv80;          // x_w
        }
        __syncthreads();

        // Fold both channels' outer products into g_ys[k] (1 atomic per (m,l))
        if (t < L) {
            float ym0 = s_mean[t];
            float ym1 = s_mean[160 + t];
            float* __restrict__ ysg = g_ys + k * (MIP * L);
            #pragma unroll
            for (int m = 0; m < MIP; m++)
                atomicAdd(ysg + m * L + t, wfc0[m] * ym0 + wfc1[m] * ym1);
        }
        __threadfence();
        __syncthreads();
        if (t == 0) atomicAdd(&g_cnt[k], 1);

        if (k >= 2) do_C(k - 2);
    }
    do_C(NB - 2);
    do_C(NB - 1);
}

// ---------------------------------------------------------------------------
extern "C" void kernel_launch(void* const* d_in, const int* in_sizes, int n_in,
                              void* d_out, int out_size) {
    const float* x        = (const float*)d_in[0];
    const float* w_fc     = (const float*)d_in[1];
    const float* bn_gamma = (const float*)d_in[2];
    const float* bn_beta  = (const float*)d_in[3];
    const float* bn_mean  = (const float*)d_in[4];
    const float* bn_var   = (const float*)d_in[5];
    const float* w_h      = (const float*)d_in[6];
    const float* w_w      = (const float*)d_in[7];
    float* out = (float*)d_out;

    static int smem_set = 0;
    if (!smem_set) {
        cudaFuncSetAttribute(fused, cudaFuncAttributeMaxDynamicSharedMemorySize,
                             SM_FLOATS * sizeof(float));
        smem_set = 1;
    }

    init_state<<<(NB * MIP * L + 255) / 256, 256>>>();
    fused<<<GRID, TPB, SM_FLOATS * sizeof(float)>>>(x, w_fc, bn_gamma, bn_beta,
                                                    bn_mean, bn_var, w_h, w_w, out);
}